// round 2
// baseline (speedup 1.0000x reference)
#include <cuda_runtime.h>
#include <cstdint>

#define NEGF (-9000000000000000.0f)

// Packed adjacency bitmask: 1024 rows x 32 words (bit j%32 of word j/32 set iff adj[i][j]>0)
__device__ uint32_t g_adjbits[1024 * 32];
// c[0] = dot(W, a[0:128]), c[1] = dot(W, a[128:256])
__device__ float g_c[2];

static constexpr int N = 1024;
static constexpr int BS = 32;
static constexpr int F = 128;
static constexpr int ROWS_PER_BLOCK = 8;

// ---------------------------------------------------------------------------
// Prep 1: c1, c2 (single warp)
// ---------------------------------------------------------------------------
__global__ void prep_c_kernel(const float* __restrict__ W, const float* __restrict__ a) {
    int lane = threadIdx.x;  // 32 threads
    float s1 = 0.f, s2 = 0.f;
#pragma unroll
    for (int k = 0; k < 4; k++) {
        int f = lane + k * 32;
        float w = W[f];
        s1 = fmaf(w, a[f], s1);
        s2 = fmaf(w, a[F + f], s2);
    }
#pragma unroll
    for (int o = 16; o; o >>= 1) {
        s1 += __shfl_xor_sync(0xFFFFFFFFu, s1, o);
        s2 += __shfl_xor_sync(0xFFFFFFFFu, s2, o);
    }
    if (lane == 0) { g_c[0] = s1; g_c[1] = s2; }
}

// ---------------------------------------------------------------------------
// Prep 2: pack adj (1024x1024 int32) into bitmask via warp ballot.
// One thread per adj element; warp = 32 consecutive j -> one word.
// ---------------------------------------------------------------------------
__global__ void prep_bits_kernel(const int* __restrict__ adj) {
    int idx = blockIdx.x * blockDim.x + threadIdx.x;  // 1M threads
    int v = adj[idx];
    unsigned ballot = __ballot_sync(0xFFFFFFFFu, v > 0);
    if ((threadIdx.x & 31) == 0) g_adjbits[idx >> 5] = ballot;
}

// ---------------------------------------------------------------------------
// Main: warp per (b, i) row. Block = 8 warps (8 rows, same batch b).
// Grid = (N / ROWS_PER_BLOCK, BS).
// ---------------------------------------------------------------------------
__global__ __launch_bounds__(256) void gat_main_kernel(
    const float* __restrict__ x,   // (BS, N)
    const float* __restrict__ W,   // (F)
    float* __restrict__ out)       // (BS, N, F)
{
    __shared__ __align__(16) float xs[N];
    __shared__ __align__(16) float Ws[F];

    const int b = blockIdx.y;
    const int tid = threadIdx.x;

    // Stage x[b, :] (vectorized: 256 threads x float4 = 1024 floats)
    reinterpret_cast<float4*>(xs)[tid] =
        reinterpret_cast<const float4*>(x + (size_t)b * N)[tid];
    if (tid < F) Ws[tid] = W[tid];
    __syncthreads();

    const float c1 = g_c[0];
    const float c2 = g_c[1];
    const int warp = tid >> 5;
    const int lane = tid & 31;
    const int i = blockIdx.x * ROWS_PER_BLOCK + warp;

    const float si = c1 * xs[i];

    // Each lane owns its adjacency word i*32+lane; word k is broadcast via shfl.
    const unsigned myword = g_adjbits[i * 32 + lane];

    float att[32];
    float mx = NEGF;
#pragma unroll
    for (int k = 0; k < 32; k++) {
        const unsigned wk = __shfl_sync(0xFFFFFFFFu, myword, k);
        const float xj = xs[k * 32 + lane];          // conflict-free
        const float e = fmaf(c2, xj, si);
        const bool keep = ((wk >> lane) & 1u) && (e > 0.f);
        const float v = keep ? e : NEGF;
        att[k] = v;
        mx = fmaxf(mx, v);
    }
    // Row max across warp
#pragma unroll
    for (int o = 16; o; o >>= 1) mx = fmaxf(mx, __shfl_xor_sync(0xFFFFFFFFu, mx, o));

    // exp + weighted sum. Note: all-masked row -> mx == NEGF,
    // att[k]-mx == 0 exactly -> p == 1 for all j -> uniform weights (matches jax softmax).
    float se = 0.f, sx = 0.f;
#pragma unroll
    for (int k = 0; k < 32; k++) {
        const float p = __expf(att[k] - mx);
        se += p;
        sx = fmaf(p, xs[k * 32 + lane], sx);
    }
#pragma unroll
    for (int o = 16; o; o >>= 1) {
        se += __shfl_xor_sync(0xFFFFFFFFu, se, o);
        sx += __shfl_xor_sync(0xFFFFFFFFu, sx, o);
    }
    const float y = sx / se;

    // Epilogue: out[b, i, f] = elu(y * W[f]); float4 store per lane.
    float4 wv = reinterpret_cast<const float4*>(Ws)[lane];
    float4 ov;
    {
        float v0 = y * wv.x; ov.x = v0 > 0.f ? v0 : expm1f(v0);
        float v1 = y * wv.y; ov.y = v1 > 0.f ? v1 : expm1f(v1);
        float v2 = y * wv.z; ov.z = v2 > 0.f ? v2 : expm1f(v2);
        float v3 = y * wv.w; ov.w = v3 > 0.f ? v3 : expm1f(v3);
    }
    reinterpret_cast<float4*>(out + ((size_t)b * N + i) * F)[lane] = ov;
}

// ---------------------------------------------------------------------------
// Launch. Inputs (metadata order): input(32*1024), adj(1024*1024),
// ext_input(unused), side_input(unused), W(128), a(256). Output: (32,1024,128) f32.
// ---------------------------------------------------------------------------
extern "C" void kernel_launch(void* const* d_in, const int* in_sizes, int n_in,
                              void* d_out, int out_size) {
    const float* x   = (const float*)d_in[0];
    const int*   adj = (const int*)d_in[1];
    const float* W   = (const float*)d_in[4];
    const float* a   = (const float*)d_in[5];
    float* out = (float*)d_out;

    prep_c_kernel<<<1, 32>>>(W, a);
    prep_bits_kernel<<<(N * N) / 256, 256>>>(adj);
    dim3 grid(N / ROWS_PER_BLOCK, BS);
    gat_main_kernel<<<grid, 256>>>(x, W, out);
}

// round 4
// speedup vs baseline: 1.2182x; 1.2182x over previous
#include <cuda_runtime.h>
#include <cstdint>

static constexpr int N   = 1024;
static constexpr int BS  = 32;
static constexpr int F   = 128;
static constexpr int RPB = 8;    // rows per block (one warp per row)

// Packed adjacency bitmask: row i -> 32 words; bit (j%32) of word (j/32) set iff adj[i][j] > 0
__device__ uint32_t g_adjbits[N * 32];

// ---------------------------------------------------------------------------
// Prep: pack adj (1024x1024 int32) into bitmask via warp ballot.
// ---------------------------------------------------------------------------
__global__ void prep_bits_kernel(const int* __restrict__ adj) {
    int idx = blockIdx.x * blockDim.x + threadIdx.x;  // 1M threads
    unsigned ballot = __ballot_sync(0xFFFFFFFFu, adj[idx] > 0);
    if ((threadIdx.x & 31) == 0) g_adjbits[idx >> 5] = ballot;
}

// ---------------------------------------------------------------------------
// Main: warp per (b, i) row. Block = 8 warps (8 rows, one batch).
// Grid = (N/RPB, BS).
//
// Math: h = x W (rank-1) => s1 = c1*x, s2 = c2*x with c1 = W.a1, c2 = W.a2.
// softmax weight exp(si + c2 xj) = exp(si)*E_j with E_j = exp(c2 xj); exp(si)
// cancels in (sum E_j xj)/(sum E_j). Keep-test identical to prior kernel:
// e = fmaf(c2, xj, si) > 0 AND adj bit. All-masked row -> se == 0 exactly ->
// uniform softmax -> y = mean_j x[b,j].
// ---------------------------------------------------------------------------
__global__ __launch_bounds__(256) void gat_main_kernel(
    const float* __restrict__ x,   // (BS, N)
    const float* __restrict__ W,   // (F)
    const float* __restrict__ a,   // (2F)
    float* __restrict__ out)       // (BS, N, F)
{
    __shared__ __align__(16) float2  xe[N];        // (xj, exp(c2*xj)) per j
    __shared__ __align__(16) float   Ws[F];
    __shared__ unsigned              wsm[RPB * 32];
    __shared__ float                 cs[2];

    const int b    = blockIdx.y;
    const int tid  = threadIdx.x;
    const int warp = tid >> 5;
    const int lane = tid & 31;
    const int i    = blockIdx.x * RPB + warp;

    // Stage x[b,:] (float4 per thread) — E written in phase 2 once c2 is known.
    const float4 xv = reinterpret_cast<const float4*>(x + (size_t)b * N)[tid];
    if (tid < F) Ws[tid] = W[tid];

    // Warp 0 computes c1 = W.a[0:F], c2 = W.a[F:2F] (block-local, cheap).
    if (warp == 0) {
        float s1 = 0.f, s2 = 0.f;
#pragma unroll
        for (int k = 0; k < 4; k++) {
            int f = lane + k * 32;
            float w = W[f];
            s1 = fmaf(w, a[f], s1);
            s2 = fmaf(w, a[F + f], s2);
        }
#pragma unroll
        for (int o = 16; o; o >>= 1) {
            s1 += __shfl_xor_sync(0xFFFFFFFFu, s1, o);
            s2 += __shfl_xor_sync(0xFFFFFFFFu, s2, o);
        }
        if (lane == 0) { cs[0] = s1; cs[1] = s2; }
    }

    // Stage this block's adjacency words (row i -> 32 words).
    wsm[warp * 32 + lane] = g_adjbits[i * 32 + lane];
    __syncthreads();

    const float c1 = cs[0];
    const float c2 = cs[1];

    // Phase 2: write (xj, E_j) pairs. 4 exps per thread; 32K exps per launch total-equivalent.
    {
        const int j0 = tid * 4;
        xe[j0 + 0] = make_float2(xv.x, __expf(c2 * xv.x));
        xe[j0 + 1] = make_float2(xv.y, __expf(c2 * xv.y));
        xe[j0 + 2] = make_float2(xv.z, __expf(c2 * xv.z));
        xe[j0 + 3] = make_float2(xv.w, __expf(c2 * xv.w));
    }
    __syncthreads();

    const float    si    = c1 * xe[i].x;
    const unsigned mybit = 1u << lane;

    float se = 0.f, sx = 0.f;
#pragma unroll
    for (int k = 0; k < 32; k++) {
        const unsigned wk = wsm[warp * 32 + k];          // LDS broadcast
        const float2   pe = xe[k * 32 + lane];           // LDS.64, conflict-free
        const float    e  = fmaf(c2, pe.x, si);          // same keep-test as R2
        if ((wk & mybit) && e > 0.f) {                   // -> predicated adds
            se += pe.y;
            sx  = fmaf(pe.y, pe.x, sx);
        }
    }
#pragma unroll
    for (int o = 16; o; o >>= 1) {
        se += __shfl_xor_sync(0xFFFFFFFFu, se, o);
        sx += __shfl_xor_sync(0xFFFFFFFFu, sx, o);
    }

    float y;
    if (se > 0.f) {                       // warp-uniform branch
        y = sx / se;
    } else {                              // all masked: uniform softmax -> mean(x)
        float s = 0.f;
#pragma unroll
        for (int k = 0; k < 32; k++) s += xe[k * 32 + lane].x;
#pragma unroll
        for (int o = 16; o; o >>= 1) s += __shfl_xor_sync(0xFFFFFFFFu, s, o);
        y = s * (1.0f / (float)N);
    }

    // Epilogue: out[b,i,f] = elu(y * W[f]); float4 per lane.
    const float4 wv = reinterpret_cast<const float4*>(Ws)[lane];
    float4 ov;
    {
        float v0 = y * wv.x; ov.x = v0 > 0.f ? v0 : expm1f(v0);
        float v1 = y * wv.y; ov.y = v1 > 0.f ? v1 : expm1f(v1);
        float v2 = y * wv.z; ov.z = v2 > 0.f ? v2 : expm1f(v2);
        float v3 = y * wv.w; ov.w = v3 > 0.f ? v3 : expm1f(v3);
    }
    reinterpret_cast<float4*>(out + ((size_t)b * N + i) * F)[lane] = ov;
}

// ---------------------------------------------------------------------------
// Launch. Inputs (metadata order): input(32*1024), adj(1024*1024),
// ext_input(unused), side_input(unused), W(128), a(256). Output: (32,1024,128) f32.
// ---------------------------------------------------------------------------
extern "C" void kernel_launch(void* const* d_in, const int* in_sizes, int n_in,
                              void* d_out, int out_size) {
    const float* x   = (const float*)d_in[0];
    const int*   adj = (const int*)d_in[1];
    const float* W   = (const float*)d_in[4];
    const float* a   = (const float*)d_in[5];
    float* out = (float*)d_out;

    prep_bits_kernel<<<(N * N) / 256, 256>>>(adj);
    dim3 grid(N / RPB, BS);
    gat_main_kernel<<<grid, 256>>>(x, W, a, out);
}

// round 8
// speedup vs baseline: 1.3101x; 1.0755x over previous
#include <cuda_runtime.h>
#include <cstdint>

static constexpr int N   = 1024;
static constexpr int BS  = 32;
static constexpr int F   = 128;
static constexpr int RPB = 8;    // rows per block (one warp per row)

// Packed adjacency bitmask: row i -> 32 words; bit (j%32) of word (j/32) set iff adj[i][j] > 0
__device__ uint32_t g_adjbits[N * 32];
// Per (b, j): (E_j = exp(c2*x_bj), x_bj)
__device__ float2   g_exq[BS * N];
// c1 = W.a[0:F], c2 = W.a[F:2F]
__device__ float    g_c[2];

// ---------------------------------------------------------------------------
// Prep (one launch, role-split by blockIdx):
//   blocks [0, 4096): pack adj bits via ballot
//   blocks [4096, 4128): per-batch (E, x) table; block 4096 also publishes c1,c2
// ---------------------------------------------------------------------------
__global__ __launch_bounds__(256) void prep_kernel(
    const int* __restrict__ adj, const float* __restrict__ x,
    const float* __restrict__ W, const float* __restrict__ a)
{
    const int blk = blockIdx.x;
    const int tid = threadIdx.x;

    if (blk < (N * N) / 256) {
        const int idx = blk * 256 + tid;
        const unsigned ballot = __ballot_sync(0xFFFFFFFFu, adj[idx] > 0);
        if ((tid & 31) == 0) g_adjbits[idx >> 5] = ballot;
        return;
    }

    // (E, x) table for batch b
    const int b = blk - (N * N) / 256;
    __shared__ float cs[2];
    const int lane = tid & 31;

    if (tid < 32) {
        float s1 = 0.f, s2 = 0.f;
#pragma unroll
        for (int k = 0; k < 4; k++) {
            const int f = lane + k * 32;
            const float w = W[f];
            s1 = fmaf(w, a[f], s1);
            s2 = fmaf(w, a[F + f], s2);
        }
#pragma unroll
        for (int o = 16; o; o >>= 1) {
            s1 += __shfl_xor_sync(0xFFFFFFFFu, s1, o);
            s2 += __shfl_xor_sync(0xFFFFFFFFu, s2, o);
        }
        if (lane == 0) {
            cs[0] = s1; cs[1] = s2;
            if (b == 0) { g_c[0] = s1; g_c[1] = s2; }
        }
    }
    __syncthreads();

    const float c2 = cs[1];
    const float4 xv = reinterpret_cast<const float4*>(x + (size_t)b * N)[tid];
    float2* dst = g_exq + (size_t)b * N + tid * 4;
    dst[0] = make_float2(__expf(c2 * xv.x), xv.x);
    dst[1] = make_float2(__expf(c2 * xv.y), xv.y);
    dst[2] = make_float2(__expf(c2 * xv.z), xv.z);
    dst[3] = make_float2(__expf(c2 * xv.w), xv.w);
}

// ---------------------------------------------------------------------------
// Main: warp per (b, i) row. Block = 8 warps (8 rows, one batch).
// Grid = (N/RPB, BS).
//
// softmax weight exp(si + c2 xj) = exp(si)*E_j; exp(si) cancels in
// (sum E_j xj)/(sum E_j). Keep-test identical to R2/R4:
// e = fmaf(c2, xj, si) > 0 AND adj bit. All-masked row -> se == 0 exactly ->
// uniform softmax -> y = mean_j x[b,j].
// ---------------------------------------------------------------------------
__global__ __launch_bounds__(256, 4) void gat_main_kernel(
    const float* __restrict__ W,
    float* __restrict__ out)       // (BS, N, F)
{
    __shared__ __align__(16) float2  xe[N];        // (E_j, x_j)
    __shared__ __align__(16) float   Ws[F];
    __shared__ unsigned              wsm[RPB * 32];

    const int b    = blockIdx.y;
    const int tid  = threadIdx.x;
    const int warp = tid >> 5;
    const int lane = tid & 31;
    const int i    = blockIdx.x * RPB + warp;

    // Stage (E, x) table (8 KB), adjacency words (1 KB), W (0.5 KB)
    {
        const float4* src = reinterpret_cast<const float4*>(g_exq + (size_t)b * N);
        float4* d4 = reinterpret_cast<float4*>(xe);
        d4[tid]       = src[tid];
        d4[tid + 256] = src[tid + 256];
    }
    wsm[tid & (RPB * 32 - 1)] = g_adjbits[blockIdx.x * RPB * 32 + (tid & (RPB * 32 - 1))];
    if (tid < F) Ws[tid] = W[tid];
    __syncthreads();

    const float c1 = g_c[0];
    const float c2 = g_c[1];
    const float si = c1 * xe[i].y;
    const unsigned mybit = 1u << lane;

    float se0 = 0.f, sq0 = 0.f, se1 = 0.f, sq1 = 0.f;
#pragma unroll
    for (int k = 0; k < 32; k += 2) {
        {
            const unsigned wk = wsm[warp * 32 + k];
            const float2   p  = xe[k * 32 + lane];
            const float    e  = fmaf(c2, p.y, si);
            if ((wk & mybit) && e > 0.f) {
                se0 += p.x;
                sq0  = fmaf(p.x, p.y, sq0);
            }
        }
        {
            const unsigned wk = wsm[warp * 32 + k + 1];
            const float2   p  = xe[(k + 1) * 32 + lane];
            const float    e  = fmaf(c2, p.y, si);
            if ((wk & mybit) && e > 0.f) {
                se1 += p.x;
                sq1  = fmaf(p.x, p.y, sq1);
            }
        }
    }
    float se = se0 + se1;
    float sx = sq0 + sq1;
#pragma unroll
    for (int o = 16; o; o >>= 1) {
        se += __shfl_xor_sync(0xFFFFFFFFu, se, o);
        sx += __shfl_xor_sync(0xFFFFFFFFu, sx, o);
    }

    float y;
    if (se > 0.f) {                       // warp-uniform branch
        y = sx / se;
    } else {                              // all masked: uniform softmax -> mean(x)
        float s = 0.f;
#pragma unroll
        for (int k = 0; k < 32; k++) s += xe[k * 32 + lane].y;
#pragma unroll
        for (int o = 16; o; o >>= 1) s += __shfl_xor_sync(0xFFFFFFFFu, s, o);
        y = s * (1.0f / (float)N);
    }

    // Epilogue: out[b,i,f] = elu(y * W[f]); float4 per lane.
    const float4 wv = reinterpret_cast<const float4*>(Ws)[lane];
    float4 ov;
    {
        float v0 = y * wv.x; ov.x = v0 > 0.f ? v0 : expm1f(v0);
        float v1 = y * wv.y; ov.y = v1 > 0.f ? v1 : expm1f(v1);
        float v2 = y * wv.z; ov.z = v2 > 0.f ? v2 : expm1f(v2);
        float v3 = y * wv.w; ov.w = v3 > 0.f ? v3 : expm1f(v3);
    }
    reinterpret_cast<float4*>(out + ((size_t)b * N + i) * F)[lane] = ov;
}

// ---------------------------------------------------------------------------
// Launch. Inputs (metadata order): input(32*1024), adj(1024*1024),
// ext_input(unused), side_input(unused), W(128), a(256). Output: (32,1024,128) f32.
// ---------------------------------------------------------------------------
extern "C" void kernel_launch(void* const* d_in, const int* in_sizes, int n_in,
                              void* d_out, int out_size) {
    const float* x   = (const float*)d_in[0];
    const int*   adj = (const int*)d_in[1];
    const float* W   = (const float*)d_in[4];
    const float* a   = (const float*)d_in[5];
    float* out = (float*)d_out;

    prep_kernel<<<(N * N) / 256 + BS, 256>>>(adj, x, W, a);
    dim3 grid(N / RPB, BS);
    gat_main_kernel<<<grid, 256>>>(W, out);
}

// round 9
// speedup vs baseline: 1.3905x; 1.0613x over previous
#include <cuda_runtime.h>
#include <cstdint>

static constexpr int N   = 1024;
static constexpr int BS  = 32;
static constexpr int F   = 128;
static constexpr int RPW = 2;     // rows per warp
static constexpr int RPB = 8 * RPW; // rows per block (8 warps)

// Transposed adjacency bitmask: word (i, c) has bit k set iff adj[i][k*32+c] > 0
__device__ uint32_t g_adjbitsT[N * 32];
// Per (b, j): (E_j = exp(c2*x_bj), x_bj)
__device__ float2   g_exq[BS * N];
// c1 = W.a[0:F], c2 = W.a[F:2F]
__device__ float    g_c[2];

// ---------------------------------------------------------------------------
// Prep (one launch, role-split by blockIdx):
//   blocks [0, 128): transposed adjacency bit-pack (warp per row; lane c builds
//                    its own word: bit k = adj[i][k*32+c] > 0, coalesced LDGs)
//   blocks [128, 160): per-batch (E, x) table; batch-0 block publishes c1,c2
// ---------------------------------------------------------------------------
__global__ __launch_bounds__(256) void prep_kernel(
    const int* __restrict__ adj, const float* __restrict__ x,
    const float* __restrict__ W, const float* __restrict__ a)
{
    const int blk  = blockIdx.x;
    const int tid  = threadIdx.x;
    const int lane = tid & 31;

    if (blk < N / 8) {
        const int i = blk * 8 + (tid >> 5);
        const int* __restrict__ row = adj + (size_t)i * N;
        unsigned t = 0;
#pragma unroll
        for (int k = 0; k < 32; k++)
            t |= (row[k * 32 + lane] > 0 ? 1u : 0u) << k;
        g_adjbitsT[i * 32 + lane] = t;
        return;
    }

    // (E, x) table for batch b
    const int b = blk - N / 8;
    __shared__ float cs[2];

    if (tid < 32) {
        float s1 = 0.f, s2 = 0.f;
#pragma unroll
        for (int k = 0; k < 4; k++) {
            const int f = lane + k * 32;
            const float w = W[f];
            s1 = fmaf(w, a[f], s1);
            s2 = fmaf(w, a[F + f], s2);
        }
#pragma unroll
        for (int o = 16; o; o >>= 1) {
            s1 += __shfl_xor_sync(0xFFFFFFFFu, s1, o);
            s2 += __shfl_xor_sync(0xFFFFFFFFu, s2, o);
        }
        if (lane == 0) {
            cs[0] = s1; cs[1] = s2;
            if (b == 0) { g_c[0] = s1; g_c[1] = s2; }
        }
    }
    __syncthreads();

    const float c2 = cs[1];
    const float4 xv = reinterpret_cast<const float4*>(x + (size_t)b * N)[tid];
    float2* dst = g_exq + (size_t)b * N + tid * 4;
    dst[0] = make_float2(__expf(c2 * xv.x), xv.x);
    dst[1] = make_float2(__expf(c2 * xv.y), xv.y);
    dst[2] = make_float2(__expf(c2 * xv.z), xv.z);
    dst[3] = make_float2(__expf(c2 * xv.w), xv.w);
}

// ---------------------------------------------------------------------------
// Main: warp per 2 rows (i0, i0+1), sharing each (E_j, x_j) LDS load.
// Block = 8 warps = 16 rows of one batch. Grid = (N/16, BS).
//
// softmax weight exp(si + c2 xj) = exp(si)*E_j; exp(si) cancels in
// (sum E_j xj)/(sum E_j). Keep-test identical to R2..R8:
// e = fmaf(c2, xj, si) > 0 AND adj bit. All-masked row -> se == 0 exactly ->
// uniform softmax -> y = mean_j x[b,j].
// ---------------------------------------------------------------------------
__global__ __launch_bounds__(256, 5) void gat_main_kernel(
    const float* __restrict__ W,
    float* __restrict__ out)       // (BS, N, F)
{
    __shared__ __align__(16) float2 xe[N];   // (E_j, x_j), 8 KB

    const int b    = blockIdx.y;
    const int tid  = threadIdx.x;
    const int warp = tid >> 5;
    const int lane = tid & 31;
    const int i0   = blockIdx.x * RPB + warp * RPW;

    // Stage (E, x) table: 512 float4s over 256 threads.
    {
        const float4* src = reinterpret_cast<const float4*>(g_exq + (size_t)b * N);
        float4* d4 = reinterpret_cast<float4*>(xe);
        d4[tid]       = src[tid];
        d4[tid + 256] = src[tid + 256];
    }
    // Per-lane transposed adjacency words for both rows (coalesced LDG).
    const unsigned t0 = g_adjbitsT[(i0 + 0) * 32 + lane];
    const unsigned t1 = g_adjbitsT[(i0 + 1) * 32 + lane];
    __syncthreads();

    const float c1  = g_c[0];
    const float c2  = g_c[1];
    const float si0 = c1 * xe[i0 + 0].y;
    const float si1 = c1 * xe[i0 + 1].y;

    float se0 = 0.f, sx0 = 0.f, se1 = 0.f, sx1 = 0.f;
#pragma unroll
    for (int k = 0; k < 32; k++) {
        const float2 p  = xe[k * 32 + lane];      // shared LDS.64, conflict-free
        const float  e0 = fmaf(c2, p.y, si0);
        const float  e1 = fmaf(c2, p.y, si1);
        if ((t0 & (1u << k)) && e0 > 0.f) {
            se0 += p.x;
            sx0  = fmaf(p.x, p.y, sx0);
        }
        if ((t1 & (1u << k)) && e1 > 0.f) {
            se1 += p.x;
            sx1  = fmaf(p.x, p.y, sx1);
        }
    }
#pragma unroll
    for (int o = 16; o; o >>= 1) {
        se0 += __shfl_xor_sync(0xFFFFFFFFu, se0, o);
        sx0 += __shfl_xor_sync(0xFFFFFFFFu, sx0, o);
        se1 += __shfl_xor_sync(0xFFFFFFFFu, se1, o);
        sx1 += __shfl_xor_sync(0xFFFFFFFFu, sx1, o);
    }

    float y0, y1;
    if (se0 > 0.f) {
        y0 = sx0 / se0;
    } else {               // all masked: uniform softmax -> mean(x)
        float s = 0.f;
#pragma unroll
        for (int k = 0; k < 32; k++) s += xe[k * 32 + lane].y;
#pragma unroll
        for (int o = 16; o; o >>= 1) s += __shfl_xor_sync(0xFFFFFFFFu, s, o);
        y0 = s * (1.0f / (float)N);
    }
    if (se1 > 0.f) {
        y1 = sx1 / se1;
    } else {
        float s = 0.f;
#pragma unroll
        for (int k = 0; k < 32; k++) s += xe[k * 32 + lane].y;
#pragma unroll
        for (int o = 16; o; o >>= 1) s += __shfl_xor_sync(0xFFFFFFFFu, s, o);
        y1 = s * (1.0f / (float)N);
    }

    // Epilogue: out[b,i,f] = elu(y * W[f]); float4 per lane, 2 rows.
    const float4 wv = __ldg(&reinterpret_cast<const float4*>(W)[lane]);
    float4* orow = reinterpret_cast<float4*>(out + ((size_t)b * N + i0) * F) + lane;
    {
        float4 ov;
        float v0 = y0 * wv.x; ov.x = v0 > 0.f ? v0 : expm1f(v0);
        float v1 = y0 * wv.y; ov.y = v1 > 0.f ? v1 : expm1f(v1);
        float v2 = y0 * wv.z; ov.z = v2 > 0.f ? v2 : expm1f(v2);
        float v3 = y0 * wv.w; ov.w = v3 > 0.f ? v3 : expm1f(v3);
        orow[0] = ov;
    }
    {
        float4 ov;
        float v0 = y1 * wv.x; ov.x = v0 > 0.f ? v0 : expm1f(v0);
        float v1 = y1 * wv.y; ov.y = v1 > 0.f ? v1 : expm1f(v1);
        float v2 = y1 * wv.z; ov.z = v2 > 0.f ? v2 : expm1f(v2);
        float v3 = y1 * wv.w; ov.w = v3 > 0.f ? v3 : expm1f(v3);
        orow[F / 4] = ov;
    }
}

// ---------------------------------------------------------------------------
// Launch. Inputs (metadata order): input(32*1024), adj(1024*1024),
// ext_input(unused), side_input(unused), W(128), a(256). Output: (32,1024,128) f32.
// ---------------------------------------------------------------------------
extern "C" void kernel_launch(void* const* d_in, const int* in_sizes, int n_in,
                              void* d_out, int out_size) {
    const float* x   = (const float*)d_in[0];
    const int*   adj = (const int*)d_in[1];
    const float* W   = (const float*)d_in[4];
    const float* a   = (const float*)d_in[5];
    float* out = (float*)d_out;

    prep_kernel<<<N / 8 + BS, 256>>>(adj, x, W, a);
    dim3 grid(N / RPB, BS);
    gat_main_kernel<<<grid, 256>>>(W, out);
}

// round 11
// speedup vs baseline: 1.4171x; 1.0191x over previous
#include <cuda_runtime.h>
#include <cstdint>

static constexpr int N   = 1024;
static constexpr int BS  = 32;
static constexpr int F   = 128;
static constexpr int RPW = 2;       // rows per warp
static constexpr int RPB = 8 * RPW; // rows per block (8 warps)

// Transposed adjacency bitmask: word (i, c) has bit k set iff adj[i][k*32+c] > 0
__device__ uint32_t g_adjbitsT[N * 32];
// Per (b, j): (x_j, E_j = exp(c2*x_j), E_j*x_j, c1*x_j)
__device__ float4   g_exq4[BS * N];
// c1 = W.a[0:F], c2 = W.a[F:2F]
__device__ float    g_c[2];

// ---------------------------------------------------------------------------
// Prep (one launch, role-split by blockIdx):
//   blocks [0, 128): transposed adjacency bit-pack (warp per row; lane c builds
//                    its word: bit k = adj[i][k*32+c] > 0, coalesced LDGs)
//   blocks [128, 160): per-batch float4 table; batch-0 block publishes c1,c2
// ---------------------------------------------------------------------------
__global__ __launch_bounds__(256) void prep_kernel(
    const int* __restrict__ adj, const float* __restrict__ x,
    const float* __restrict__ W, const float* __restrict__ a)
{
    const int blk  = blockIdx.x;
    const int tid  = threadIdx.x;
    const int lane = tid & 31;

    if (blk < N / 8) {
        const int i = blk * 8 + (tid >> 5);
        const int* __restrict__ row = adj + (size_t)i * N;
        unsigned t = 0;
#pragma unroll
        for (int k = 0; k < 32; k++)
            t |= (row[k * 32 + lane] > 0 ? 1u : 0u) << k;
        g_adjbitsT[i * 32 + lane] = t;
        return;
    }

    const int b = blk - N / 8;
    __shared__ float cs[2];

    if (tid < 32) {
        float s1 = 0.f, s2 = 0.f;
#pragma unroll
        for (int k = 0; k < 4; k++) {
            const int f = lane + k * 32;
            const float w = W[f];
            s1 = fmaf(w, a[f], s1);
            s2 = fmaf(w, a[F + f], s2);
        }
#pragma unroll
        for (int o = 16; o; o >>= 1) {
            s1 += __shfl_xor_sync(0xFFFFFFFFu, s1, o);
            s2 += __shfl_xor_sync(0xFFFFFFFFu, s2, o);
        }
        if (lane == 0) {
            cs[0] = s1; cs[1] = s2;
            if (b == 0) { g_c[0] = s1; g_c[1] = s2; }
        }
    }
    __syncthreads();

    const float c1 = cs[0];
    const float c2 = cs[1];
    const float4 xv = reinterpret_cast<const float4*>(x + (size_t)b * N)[tid];
    float4* dst = g_exq4 + (size_t)b * N + tid * 4;
    {
        float E = __expf(c2 * xv.x);
        dst[0] = make_float4(xv.x, E, E * xv.x, c1 * xv.x);
    }
    {
        float E = __expf(c2 * xv.y);
        dst[1] = make_float4(xv.y, E, E * xv.y, c1 * xv.y);
    }
    {
        float E = __expf(c2 * xv.z);
        dst[2] = make_float4(xv.z, E, E * xv.z, c1 * xv.z);
    }
    {
        float E = __expf(c2 * xv.w);
        dst[3] = make_float4(xv.w, E, E * xv.w, c1 * xv.w);
    }
}

// ---------------------------------------------------------------------------
// Main: warp per 2 rows (i0, i0+1), sharing each table LDS.128.
// Block = 8 warps = 16 rows of one batch. Grid = (N/16, BS).
//
// softmax weight exp(si + c2 xj) = exp(si)*E_j; exp(si) cancels in
// (sum E_j xj)/(sum E_j). Keep-test identical to R2..R9:
// e = fmaf(c2, xj, si) > 0 AND adj bit, with si = c1*x_i (single rounding,
// computed in prep -> .w). Conditional arm is 2 plain FADDs (E, E*x precomputed)
// so ptxas predicates it — no BSSY/BRA in the hot loop.
// All-masked row -> se == 0 exactly -> uniform softmax -> y = mean_j x[b,j].
// ---------------------------------------------------------------------------
__global__ __launch_bounds__(256, 6) void gat_main_kernel(
    const float* __restrict__ W,
    float* __restrict__ out)       // (BS, N, F)
{
    __shared__ __align__(16) float4 xs[N];   // (x, E, Ex, c1*x), 16 KB

    const int b    = blockIdx.y;
    const int tid  = threadIdx.x;
    const int warp = tid >> 5;
    const int lane = tid & 31;
    const int i0   = blockIdx.x * RPB + warp * RPW;

    // Stage table: 1024 float4s over 256 threads (4 each).
    {
        const float4* src = g_exq4 + (size_t)b * N;
#pragma unroll
        for (int q = 0; q < 4; q++)
            xs[tid + q * 256] = src[tid + q * 256];
    }
    // Per-lane transposed adjacency words for both rows (coalesced LDG).
    const unsigned t0 = g_adjbitsT[(i0 + 0) * 32 + lane];
    const unsigned t1 = g_adjbitsT[(i0 + 1) * 32 + lane];
    __syncthreads();

    const float c2  = g_c[1];
    const float si0 = xs[i0 + 0].w;   // c1 * x_{i0}
    const float si1 = xs[i0 + 1].w;   // c1 * x_{i0+1}

    float se0 = 0.f, sx0 = 0.f, se1 = 0.f, sx1 = 0.f;
#pragma unroll
    for (int k = 0; k < 32; k++) {
        const float4 p  = xs[k * 32 + lane];     // LDS.128, conflict-free
        const float  e0 = fmaf(c2, p.x, si0);
        const float  e1 = fmaf(c2, p.x, si1);
        const bool q0 = ((t0 & (1u << k)) != 0u) & (e0 > 0.f);
        const bool q1 = ((t1 & (1u << k)) != 0u) & (e1 > 0.f);
        if (q0) { se0 += p.y; sx0 += p.z; }      // 2-FADD arm -> predicated
        if (q1) { se1 += p.y; sx1 += p.z; }
    }
#pragma unroll
    for (int o = 16; o; o >>= 1) {
        se0 += __shfl_xor_sync(0xFFFFFFFFu, se0, o);
        sx0 += __shfl_xor_sync(0xFFFFFFFFu, sx0, o);
        se1 += __shfl_xor_sync(0xFFFFFFFFu, se1, o);
        sx1 += __shfl_xor_sync(0xFFFFFFFFu, sx1, o);
    }

    float y0, y1;
    if (se0 > 0.f) {
        y0 = sx0 / se0;
    } else {               // all masked: uniform softmax -> mean(x)
        float s = 0.f;
#pragma unroll
        for (int k = 0; k < 32; k++) s += xs[k * 32 + lane].x;
#pragma unroll
        for (int o = 16; o; o >>= 1) s += __shfl_xor_sync(0xFFFFFFFFu, s, o);
        y0 = s * (1.0f / (float)N);
    }
    if (se1 > 0.f) {
        y1 = sx1 / se1;
    } else {
        float s = 0.f;
#pragma unroll
        for (int k = 0; k < 32; k++) s += xs[k * 32 + lane].x;
#pragma unroll
        for (int o = 16; o; o >>= 1) s += __shfl_xor_sync(0xFFFFFFFFu, s, o);
        y1 = s * (1.0f / (float)N);
    }

    // Epilogue: out[b,i,f] = elu(y * W[f]); float4 per lane, 2 rows.
    const float4 wv = __ldg(&reinterpret_cast<const float4*>(W)[lane]);
    float4* orow = reinterpret_cast<float4*>(out + ((size_t)b * N + i0) * F) + lane;
    {
        float4 ov;
        float v0 = y0 * wv.x; ov.x = v0 > 0.f ? v0 : expm1f(v0);
        float v1 = y0 * wv.y; ov.y = v1 > 0.f ? v1 : expm1f(v1);
        float v2 = y0 * wv.z; ov.z = v2 > 0.f ? v2 : expm1f(v2);
        float v3 = y0 * wv.w; ov.w = v3 > 0.f ? v3 : expm1f(v3);
        orow[0] = ov;
    }
    {
        float4 ov;
        float v0 = y1 * wv.x; ov.x = v0 > 0.f ? v0 : expm1f(v0);
        float v1 = y1 * wv.y; ov.y = v1 > 0.f ? v1 : expm1f(v1);
        float v2 = y1 * wv.z; ov.z = v2 > 0.f ? v2 : expm1f(v2);
        float v3 = y1 * wv.w; ov.w = v3 > 0.f ? v3 : expm1f(v3);
        orow[F / 4] = ov;
    }
}

// ---------------------------------------------------------------------------
// Launch. Inputs (metadata order): input(32*1024), adj(1024*1024),
// ext_input(unused), side_input(unused), W(128), a(256). Output: (32,1024,128) f32.
// ---------------------------------------------------------------------------
extern "C" void kernel_launch(void* const* d_in, const int* in_sizes, int n_in,
                              void* d_out, int out_size) {
    const float* x   = (const float*)d_in[0];
    const int*   adj = (const int*)d_in[1];
    const float* W   = (const float*)d_in[4];
    const float* a   = (const float*)d_in[5];
    float* out = (float*)d_out;

    prep_kernel<<<N / 8 + BS, 256>>>(adj, x, W, a);
    dim3 grid(N / RPB, BS);
    gat_main_kernel<<<grid, 256>>>(W, out);
}

// round 12
// speedup vs baseline: 1.4335x; 1.0116x over previous
#include <cuda_runtime.h>
#include <cstdint>

static constexpr int N     = 1024;
static constexpr int BS    = 32;
static constexpr int F     = 128;
static constexpr int RPW   = 4;              // rows per warp
static constexpr int WARPS = 16;
static constexpr int RPB   = WARPS * RPW;    // 64 rows per block
static constexpr int THREADS = WARPS * 32;   // 512

// Transposed adjacency bitmask: word (i, c) has bit k set iff adj[i][k*32+c] > 0
__device__ uint32_t g_adjbitsT[N * 32];
// Per (b, j): (E_j = exp(c2*x_j), E_j*x_j, x_j, c1*x_j)
__device__ float4   g_tab[BS * N];
// c1 = W.a[0:F], c2 = W.a[F:2F]
__device__ float    g_c[2];

// ---------------------------------------------------------------------------
// Prep (one launch, role-split by blockIdx):
//   blocks [0, 128): transposed adjacency bit-pack (warp per row, coalesced)
//   blocks [128, 160): per-batch float4 table; batch-0 block publishes c1,c2
// ---------------------------------------------------------------------------
__global__ __launch_bounds__(256) void prep_kernel(
    const int* __restrict__ adj, const float* __restrict__ x,
    const float* __restrict__ W, const float* __restrict__ a)
{
    const int blk  = blockIdx.x;
    const int tid  = threadIdx.x;
    const int lane = tid & 31;

    if (blk < N / 8) {
        const int i = blk * 8 + (tid >> 5);
        const int* __restrict__ row = adj + (size_t)i * N;
        unsigned t = 0;
#pragma unroll
        for (int k = 0; k < 32; k++)
            t |= (row[k * 32 + lane] > 0 ? 1u : 0u) << k;
        g_adjbitsT[i * 32 + lane] = t;
        return;
    }

    const int b = blk - N / 8;
    __shared__ float cs[2];

    if (tid < 32) {
        float s1 = 0.f, s2 = 0.f;
#pragma unroll
        for (int k = 0; k < 4; k++) {
            const int f = lane + k * 32;
            const float w = W[f];
            s1 = fmaf(w, a[f], s1);
            s2 = fmaf(w, a[F + f], s2);
        }
#pragma unroll
        for (int o = 16; o; o >>= 1) {
            s1 += __shfl_xor_sync(0xFFFFFFFFu, s1, o);
            s2 += __shfl_xor_sync(0xFFFFFFFFu, s2, o);
        }
        if (lane == 0) {
            cs[0] = s1; cs[1] = s2;
            if (b == 0) { g_c[0] = s1; g_c[1] = s2; }
        }
    }
    __syncthreads();

    const float c1 = cs[0];
    const float c2 = cs[1];
    const float4 xv = reinterpret_cast<const float4*>(x + (size_t)b * N)[tid];
    float4* dst = g_tab + (size_t)b * N + tid * 4;
    { float E = __expf(c2 * xv.x); dst[0] = make_float4(E, E * xv.x, xv.x, c1 * xv.x); }
    { float E = __expf(c2 * xv.y); dst[1] = make_float4(E, E * xv.y, xv.y, c1 * xv.y); }
    { float E = __expf(c2 * xv.z); dst[2] = make_float4(E, E * xv.z, xv.z, c1 * xv.z); }
    { float E = __expf(c2 * xv.w); dst[3] = make_float4(E, E * xv.w, xv.w, c1 * xv.w); }
}

// Predicated packed accumulate: acc (se,sx as f32x2) += (E,Ex) iff
// (t & m) != 0 AND e > 0.  Keep-test identical to R2..R11.
#define GAT_ROW(acc, e, t, m, pair)                                   \
    asm volatile("{\n\t"                                              \
        ".reg .pred pb;\n\t"                                          \
        ".reg .b32  rr;\n\t"                                          \
        "and.b32 rr, %2, %3;\n\t"                                     \
        "setp.ne.b32 pb, rr, 0;\n\t"                                  \
        "setp.gt.and.f32 pb, %1, 0f00000000, pb;\n\t"                 \
        "@pb add.rn.f32x2 %0, %0, %4;\n\t"                            \
        "}" : "+l"(acc) : "f"(e), "r"(t), "r"(m), "l"(pair))

// ---------------------------------------------------------------------------
// Main: warp handles 4 rows (i0..i0+3), all sharing each table LDS.128.
// Block = 16 warps = 64 rows of one batch. Grid = (N/64, BS).
// softmax weight exp(si + c2 xj) = exp(si)*E_j; exp(si) cancels in
// (sum E_j xj)/(sum E_j). All-masked row -> se == 0 -> uniform -> mean(x).
// ---------------------------------------------------------------------------
__global__ __launch_bounds__(THREADS, 3) void gat_main_kernel(
    const float* __restrict__ W,
    float* __restrict__ out)       // (BS, N, F)
{
    __shared__ __align__(16) float4 xs[N];   // (E, Ex, x, c1x), 16 KB

    const int b    = blockIdx.y;
    const int tid  = threadIdx.x;
    const int warp = tid >> 5;
    const int lane = tid & 31;
    const int i0   = blockIdx.x * RPB + warp * RPW;

    // Stage table: 1024 float4s over 512 threads (2 each).
    {
        const float4* src = g_tab + (size_t)b * N;
        xs[tid]       = src[tid];
        xs[tid + 512] = src[tid + 512];
    }
    // Per-lane transposed adjacency words for the 4 rows (coalesced LDG).
    const unsigned t0 = g_adjbitsT[(i0 + 0) * 32 + lane];
    const unsigned t1 = g_adjbitsT[(i0 + 1) * 32 + lane];
    const unsigned t2 = g_adjbitsT[(i0 + 2) * 32 + lane];
    const unsigned t3 = g_adjbitsT[(i0 + 3) * 32 + lane];
    __syncthreads();

    const float c2  = g_c[1];
    const float si0 = xs[i0 + 0].w;   // c1 * x_i (rounded once, in prep)
    const float si1 = xs[i0 + 1].w;
    const float si2 = xs[i0 + 2].w;
    const float si3 = xs[i0 + 3].w;

    unsigned long long a0 = 0ull, a1 = 0ull, a2 = 0ull, a3 = 0ull; // (se, sx)
#pragma unroll
    for (int k = 0; k < 32; k++) {
        const float4 p = xs[k * 32 + lane];   // LDS.128, conflict-free
        unsigned long long pair;              // (E, Ex) packed, shared by 4 rows
        asm("mov.b64 %0, {%1, %2};"
            : "=l"(pair) : "r"(__float_as_uint(p.x)), "r"(__float_as_uint(p.y)));
        const unsigned m = 1u << k;
        const float e0 = fmaf(c2, p.z, si0);
        const float e1 = fmaf(c2, p.z, si1);
        const float e2 = fmaf(c2, p.z, si2);
        const float e3 = fmaf(c2, p.z, si3);
        GAT_ROW(a0, e0, t0, m, pair);
        GAT_ROW(a1, e1, t1, m, pair);
        GAT_ROW(a2, e2, t2, m, pair);
        GAT_ROW(a3, e3, t3, m, pair);
    }

    float se[RPW], sx[RPW];
    se[0] = __uint_as_float((unsigned)a0); sx[0] = __uint_as_float((unsigned)(a0 >> 32));
    se[1] = __uint_as_float((unsigned)a1); sx[1] = __uint_as_float((unsigned)(a1 >> 32));
    se[2] = __uint_as_float((unsigned)a2); sx[2] = __uint_as_float((unsigned)(a2 >> 32));
    se[3] = __uint_as_float((unsigned)a3); sx[3] = __uint_as_float((unsigned)(a3 >> 32));

#pragma unroll
    for (int r = 0; r < RPW; r++) {
#pragma unroll
        for (int o = 16; o; o >>= 1) {
            se[r] += __shfl_xor_sync(0xFFFFFFFFu, se[r], o);
            sx[r] += __shfl_xor_sync(0xFFFFFFFFu, sx[r], o);
        }
    }

    const float4 wv = __ldg(&reinterpret_cast<const float4*>(W)[lane]);
    float4* orow = reinterpret_cast<float4*>(out + ((size_t)b * N + i0) * F) + lane;

#pragma unroll
    for (int r = 0; r < RPW; r++) {
        float y;
        if (se[r] > 0.f) {
            y = sx[r] / se[r];
        } else {           // all masked: uniform softmax -> mean(x)
            float s = 0.f;
#pragma unroll
            for (int k = 0; k < 32; k++) s += xs[k * 32 + lane].z;
#pragma unroll
            for (int o = 16; o; o >>= 1) s += __shfl_xor_sync(0xFFFFFFFFu, s, o);
            y = s * (1.0f / (float)N);
        }
        float4 ov;
        float v0 = y * wv.x; ov.x = v0 > 0.f ? v0 : expm1f(v0);
        float v1 = y * wv.y; ov.y = v1 > 0.f ? v1 : expm1f(v1);
        float v2 = y * wv.z; ov.z = v2 > 0.f ? v2 : expm1f(v2);
        float v3 = y * wv.w; ov.w = v3 > 0.f ? v3 : expm1f(v3);
        orow[r * (F / 4)] = ov;
    }
}

// ---------------------------------------------------------------------------
// Launch. Inputs (metadata order): input(32*1024), adj(1024*1024),
// ext_input(unused), side_input(unused), W(128), a(256). Output: (32,1024,128) f32.
// ---------------------------------------------------------------------------
extern "C" void kernel_launch(void* const* d_in, const int* in_sizes, int n_in,
                              void* d_out, int out_size) {
    const float* x   = (const float*)d_in[0];
    const int*   adj = (const int*)d_in[1];
    const float* W   = (const float*)d_in[4];
    const float* a   = (const float*)d_in[5];
    float* out = (float*)d_out;

    prep_kernel<<<N / 8 + BS, 256>>>(adj, x, W, a);
    dim3 grid(N / RPB, BS);
    gat_main_kernel<<<grid, THREADS>>>(W, out);
}

// round 14
// speedup vs baseline: 1.5431x; 1.0764x over previous
#include <cuda_runtime.h>
#include <cstdint>

static constexpr int N     = 1024;
static constexpr int BS    = 32;
static constexpr int F     = 128;
static constexpr int RPW   = 4;              // rows per warp
static constexpr int WARPS = 8;              // warps per block
static constexpr int RPB   = WARPS * RPW;    // 32 rows per block
static constexpr int THREADS = WARPS * 32;   // 256

// Transposed adjacency bitmask: word (i, c) has bit k set iff adj[i][k*32+c] > 0
__device__ uint32_t g_adjbitsT[N * 32];
// Per (b, j): (x_j, E_j = exp(c2*x_j))
__device__ float2   g_tab2[BS * N];
// Per (b, i): c1 * x_i (single rounding — the keep-test si)
__device__ float    g_c1x[BS * N];
// c1 = W.a[0:F], c2 = W.a[F:2F]
__device__ float    g_c[2];

// ---------------------------------------------------------------------------
// Prep (one launch, role-split by blockIdx):
//   blocks [0, 128): transposed adjacency bit-pack (warp per row, coalesced)
//   blocks [128, 160): per-batch (x, E) table + c1*x; batch-0 publishes c1,c2
// ---------------------------------------------------------------------------
__global__ __launch_bounds__(256) void prep_kernel(
    const int* __restrict__ adj, const float* __restrict__ x,
    const float* __restrict__ W, const float* __restrict__ a)
{
    const int blk  = blockIdx.x;
    const int tid  = threadIdx.x;
    const int lane = tid & 31;

    if (blk < N / 8) {
        const int i = blk * 8 + (tid >> 5);
        const int* __restrict__ row = adj + (size_t)i * N;
        unsigned t = 0;
#pragma unroll
        for (int k = 0; k < 32; k++)
            t |= (row[k * 32 + lane] > 0 ? 1u : 0u) << k;
        g_adjbitsT[i * 32 + lane] = t;
        return;
    }

    const int b = blk - N / 8;
    __shared__ float cs[2];

    if (tid < 32) {
        float s1 = 0.f, s2 = 0.f;
#pragma unroll
        for (int k = 0; k < 4; k++) {
            const int f = lane + k * 32;
            const float w = W[f];
            s1 = fmaf(w, a[f], s1);
            s2 = fmaf(w, a[F + f], s2);
        }
#pragma unroll
        for (int o = 16; o; o >>= 1) {
            s1 += __shfl_xor_sync(0xFFFFFFFFu, s1, o);
            s2 += __shfl_xor_sync(0xFFFFFFFFu, s2, o);
        }
        if (lane == 0) {
            cs[0] = s1; cs[1] = s2;
            if (b == 0) { g_c[0] = s1; g_c[1] = s2; }
        }
    }
    __syncthreads();

    const float c1 = cs[0];
    const float c2 = cs[1];
    const float4 xv = reinterpret_cast<const float4*>(x + (size_t)b * N)[tid];
    float2* dst = g_tab2 + (size_t)b * N + tid * 4;
    dst[0] = make_float2(xv.x, __expf(c2 * xv.x));
    dst[1] = make_float2(xv.y, __expf(c2 * xv.y));
    dst[2] = make_float2(xv.z, __expf(c2 * xv.z));
    dst[3] = make_float2(xv.w, __expf(c2 * xv.w));
    reinterpret_cast<float4*>(g_c1x + (size_t)b * N)[tid] =
        make_float4(c1 * xv.x, c1 * xv.y, c1 * xv.z, c1 * xv.w);
}

// ---------------------------------------------------------------------------
// Main: warp handles 4 rows, sharing each table LDS.64.
// Block = 8 warps = 32 rows of one batch. Grid = (N/32, BS) = 1024 blocks,
// single wave at 7 blocks/SM (1036 >= 1024).
//
// softmax weight exp(si + c2 xj) = exp(si)*E_j; exp(si) cancels in
// (sum E_j xj)/(sum E_j). Keep-test identical to R2..R12:
// e = fmaf(c2, xj, si) > 0 AND adj bit, si = c1*x_i rounded once in prep.
// Conditional via value-select (FSEL, no branches): v = q ? E : 0;
// se += v; sx = fmaf(v, x, sx). All-masked row -> se == 0 -> mean(x).
// ---------------------------------------------------------------------------
__global__ __launch_bounds__(THREADS, 7) void gat_main_kernel(
    const float* __restrict__ W,
    float* __restrict__ out)       // (BS, N, F)
{
    __shared__ __align__(16) float2 xs[N];   // (x, E), 8 KB

    const int b    = blockIdx.y;
    const int tid  = threadIdx.x;
    const int warp = tid >> 5;
    const int lane = tid & 31;
    const int i0   = blockIdx.x * RPB + warp * RPW;

    // Stage table: 512 float4s over 256 threads (2 each).
    {
        const float4* src = reinterpret_cast<const float4*>(g_tab2 + (size_t)b * N);
        float4* d4 = reinterpret_cast<float4*>(xs);
        d4[tid]       = src[tid];
        d4[tid + 256] = src[tid + 256];
    }
    // Per-lane transposed adjacency words for the 4 rows (coalesced LDG).
    const unsigned t0 = g_adjbitsT[(i0 + 0) * 32 + lane];
    const unsigned t1 = g_adjbitsT[(i0 + 1) * 32 + lane];
    const unsigned t2 = g_adjbitsT[(i0 + 2) * 32 + lane];
    const unsigned t3 = g_adjbitsT[(i0 + 3) * 32 + lane];
    // si = c1 * x_i (prep-rounded; broadcast L2 loads)
    const float si0 = g_c1x[(size_t)b * N + i0 + 0];
    const float si1 = g_c1x[(size_t)b * N + i0 + 1];
    const float si2 = g_c1x[(size_t)b * N + i0 + 2];
    const float si3 = g_c1x[(size_t)b * N + i0 + 3];
    const float c2  = g_c[1];
    __syncthreads();

    float se0 = 0.f, sx0 = 0.f, se1 = 0.f, sx1 = 0.f;
    float se2 = 0.f, sx2 = 0.f, se3 = 0.f, sx3 = 0.f;
#pragma unroll
    for (int k = 0; k < 32; k++) {
        const float2 p = xs[k * 32 + lane];   // LDS.64, conflict-free
        const unsigned m = 1u << k;
        {
            const float e = fmaf(c2, p.x, si0);
            const float v = (((t0 & m) != 0u) & (e > 0.f)) ? p.y : 0.f;
            se0 += v; sx0 = fmaf(v, p.x, sx0);
        }
        {
            const float e = fmaf(c2, p.x, si1);
            const float v = (((t1 & m) != 0u) & (e > 0.f)) ? p.y : 0.f;
            se1 += v; sx1 = fmaf(v, p.x, sx1);
        }
        {
            const float e = fmaf(c2, p.x, si2);
            const float v = (((t2 & m) != 0u) & (e > 0.f)) ? p.y : 0.f;
            se2 += v; sx2 = fmaf(v, p.x, sx2);
        }
        {
            const float e = fmaf(c2, p.x, si3);
            const float v = (((t3 & m) != 0u) & (e > 0.f)) ? p.y : 0.f;
            se3 += v; sx3 = fmaf(v, p.x, sx3);
        }
    }

    float se[RPW] = {se0, se1, se2, se3};
    float sx[RPW] = {sx0, sx1, sx2, sx3};
#pragma unroll
    for (int r = 0; r < RPW; r++) {
#pragma unroll
        for (int o = 16; o; o >>= 1) {
            se[r] += __shfl_xor_sync(0xFFFFFFFFu, se[r], o);
            sx[r] += __shfl_xor_sync(0xFFFFFFFFu, sx[r], o);
        }
    }

    const float4 wv = __ldg(&reinterpret_cast<const float4*>(W)[lane]);
    float4* orow = reinterpret_cast<float4*>(out + ((size_t)b * N + i0) * F) + lane;

#pragma unroll
    for (int r = 0; r < RPW; r++) {
        float y;
        if (se[r] > 0.f) {
            y = sx[r] / se[r];
        } else {           // all masked: uniform softmax -> mean(x)
            float s = 0.f;
#pragma unroll
            for (int k = 0; k < 32; k++) s += xs[k * 32 + lane].x;
#pragma unroll
            for (int o = 16; o; o >>= 1) s += __shfl_xor_sync(0xFFFFFFFFu, s, o);
            y = s * (1.0f / (float)N);
        }
        float4 ov;
        float v0 = y * wv.x; ov.x = v0 > 0.f ? v0 : expm1f(v0);
        float v1 = y * wv.y; ov.y = v1 > 0.f ? v1 : expm1f(v1);
        float v2 = y * wv.z; ov.z = v2 > 0.f ? v2 : expm1f(v2);
        float v3 = y * wv.w; ov.w = v3 > 0.f ? v3 : expm1f(v3);
        orow[r * (F / 4)] = ov;
    }
}

// ---------------------------------------------------------------------------
// Launch. Inputs (metadata order): input(32*1024), adj(1024*1024),
// ext_input(unused), side_input(unused), W(128), a(256). Output: (32,1024,128) f32.
// ---------------------------------------------------------------------------
extern "C" void kernel_launch(void* const* d_in, const int* in_sizes, int n_in,
                              void* d_out, int out_size) {
    const float* x   = (const float*)d_in[0];
    const int*   adj = (const int*)d_in[1];
    const float* W   = (const float*)d_in[4];
    const float* a   = (const float*)d_in[5];
    float* out = (float*)d_out;

    prep_kernel<<<N / 8 + BS, 256>>>(adj, x, W, a);
    dim3 grid(N / RPB, BS);
    gat_main_kernel<<<grid, THREADS>>>(W, out);
}

// round 16
// speedup vs baseline: 1.6962x; 1.0992x over previous
#include <cuda_runtime.h>
#include <cstdint>

static constexpr int N     = 1024;
static constexpr int BS    = 32;
static constexpr int F     = 128;
static constexpr int RPW   = 4;              // rows per warp
static constexpr int WARPS = 8;              // warps per block
static constexpr int RPB   = WARPS * RPW;    // 32 rows per block
static constexpr int THREADS = WARPS * 32;   // 256

// Transposed adjacency bitmask: word (i, c) has bit k set iff adj[i][k*32+c] > 0
__device__ uint32_t g_adjbitsT[N * 32];
// Per (b, j): (u_j = c2*x_j, E_j = exp(u_j))
__device__ float2   g_tab2[BS * N];
// Per (b, i): c1 * x_i
__device__ float    g_c1x[BS * N];
// c1 = W.a[0:F], c2 = W.a[F:2F]
__device__ float    g_c[2];

// ---------------------------------------------------------------------------
// Prep (one launch, role-split by blockIdx):
//   blocks [0, 128): transposed adjacency bit-pack (warp per row, coalesced)
//   blocks [128, 160): per-batch (u, E) table + c1*x; batch-0 publishes c1,c2
// ---------------------------------------------------------------------------
__global__ __launch_bounds__(256) void prep_kernel(
    const int* __restrict__ adj, const float* __restrict__ x,
    const float* __restrict__ W, const float* __restrict__ a)
{
    const int blk  = blockIdx.x;
    const int tid  = threadIdx.x;
    const int lane = tid & 31;

    if (blk < N / 8) {
        const int i = blk * 8 + (tid >> 5);
        const int* __restrict__ row = adj + (size_t)i * N;
        unsigned t = 0;
#pragma unroll
        for (int k = 0; k < 32; k++)
            t |= (row[k * 32 + lane] > 0 ? 1u : 0u) << k;
        g_adjbitsT[i * 32 + lane] = t;
        return;
    }

    const int b = blk - N / 8;
    __shared__ float cs[2];

    if (tid < 32) {
        float s1 = 0.f, s2 = 0.f;
#pragma unroll
        for (int k = 0; k < 4; k++) {
            const int f = lane + k * 32;
            const float w = W[f];
            s1 = fmaf(w, a[f], s1);
            s2 = fmaf(w, a[F + f], s2);
        }
#pragma unroll
        for (int o = 16; o; o >>= 1) {
            s1 += __shfl_xor_sync(0xFFFFFFFFu, s1, o);
            s2 += __shfl_xor_sync(0xFFFFFFFFu, s2, o);
        }
        if (lane == 0) {
            cs[0] = s1; cs[1] = s2;
            if (b == 0) { g_c[0] = s1; g_c[1] = s2; }
        }
    }
    __syncthreads();

    const float c1 = cs[0];
    const float c2 = cs[1];
    const float4 xv = reinterpret_cast<const float4*>(x + (size_t)b * N)[tid];
    float2* dst = g_tab2 + (size_t)b * N + tid * 4;
    const float u0 = c2 * xv.x, u1 = c2 * xv.y, u2 = c2 * xv.z, u3 = c2 * xv.w;
    dst[0] = make_float2(u0, __expf(u0));
    dst[1] = make_float2(u1, __expf(u1));
    dst[2] = make_float2(u2, __expf(u2));
    dst[3] = make_float2(u3, __expf(u3));
    reinterpret_cast<float4*>(g_c1x + (size_t)b * N)[tid] =
        make_float4(c1 * xv.x, c1 * xv.y, c1 * xv.z, c1 * xv.w);
}

// ---------------------------------------------------------------------------
// Main: warp handles 4 rows, sharing each table LDS.64.
// Block = 8 warps = 32 rows of one batch. Grid = (N/32, BS) = 1024 blocks,
// single wave at 8 blocks/SM (1184 >= 1024).
//
// Keep-test (threshold form): edge kept iff adj-bit AND u_j > t_i where
// t_i = -(c1*x_i). Equivalent to fmaf(c2,x_j,si) > 0 except within 1 ulp of
// the boundary (~few edges of 33.5M; ~1e-5 global rel_err impact, budget 1e-3).
// softmax: y_i = (sum v_j * x_j)/(sum v_j) with v_j = E_j over kept set;
// we accumulate su = sum v*u = c2*sum v*x and divide by c2 once at the end.
// All-masked row -> se == 0 -> uniform softmax -> y = mean(x) = sum(u)/(c2*N).
// ---------------------------------------------------------------------------
__global__ __launch_bounds__(THREADS, 8) void gat_main_kernel(
    const float* __restrict__ W,
    float* __restrict__ out)       // (BS, N, F)
{
    __shared__ __align__(16) float2 xs[N];   // (u, E), 8 KB

    const int b    = blockIdx.y;
    const int tid  = threadIdx.x;
    const int warp = tid >> 5;
    const int lane = tid & 31;
    const int i0   = blockIdx.x * RPB + warp * RPW;

    // Stage table: 512 float4s over 256 threads (2 each).
    {
        const float4* src = reinterpret_cast<const float4*>(g_tab2 + (size_t)b * N);
        float4* d4 = reinterpret_cast<float4*>(xs);
        d4[tid]       = src[tid];
        d4[tid + 256] = src[tid + 256];
    }
    // Per-lane transposed adjacency words for the 4 rows (coalesced LDG).
    const unsigned t0 = g_adjbitsT[(i0 + 0) * 32 + lane];
    const unsigned t1 = g_adjbitsT[(i0 + 1) * 32 + lane];
    const unsigned t2 = g_adjbitsT[(i0 + 2) * 32 + lane];
    const unsigned t3 = g_adjbitsT[(i0 + 3) * 32 + lane];
    // Thresholds: ti = -(c1*x_i)  (prep-rounded c1*x_i; broadcast L2 loads)
    const float ti0 = -g_c1x[(size_t)b * N + i0 + 0];
    const float ti1 = -g_c1x[(size_t)b * N + i0 + 1];
    const float ti2 = -g_c1x[(size_t)b * N + i0 + 2];
    const float ti3 = -g_c1x[(size_t)b * N + i0 + 3];
    const float c2  = g_c[1];
    __syncthreads();

    float se0 = 0.f, su0 = 0.f, se1 = 0.f, su1 = 0.f;
    float se2 = 0.f, su2 = 0.f, se3 = 0.f, su3 = 0.f;
#pragma unroll
    for (int k = 0; k < 32; k++) {
        const float2 p = xs[k * 32 + lane];   // (u, E), LDS.64 conflict-free
        const unsigned m = 1u << k;
        {
            const float v = (((t0 & m) != 0u) & (p.x > ti0)) ? p.y : 0.f;
            se0 += v; su0 = fmaf(v, p.x, su0);
        }
        {
            const float v = (((t1 & m) != 0u) & (p.x > ti1)) ? p.y : 0.f;
            se1 += v; su1 = fmaf(v, p.x, su1);
        }
        {
            const float v = (((t2 & m) != 0u) & (p.x > ti2)) ? p.y : 0.f;
            se2 += v; su2 = fmaf(v, p.x, su2);
        }
        {
            const float v = (((t3 & m) != 0u) & (p.x > ti3)) ? p.y : 0.f;
            se3 += v; su3 = fmaf(v, p.x, su3);
        }
    }

    float se[RPW] = {se0, se1, se2, se3};
    float su[RPW] = {su0, su1, su2, su3};
#pragma unroll
    for (int r = 0; r < RPW; r++) {
#pragma unroll
        for (int o = 16; o; o >>= 1) {
            se[r] += __shfl_xor_sync(0xFFFFFFFFu, se[r], o);
            su[r] += __shfl_xor_sync(0xFFFFFFFFu, su[r], o);
        }
    }

    const float4 wv = __ldg(&reinterpret_cast<const float4*>(W)[lane]);
    float4* orow = reinterpret_cast<float4*>(out + ((size_t)b * N + i0) * F) + lane;
    const float inv_c2 = 1.0f / c2;

#pragma unroll
    for (int r = 0; r < RPW; r++) {
        float y;
        if (se[r] > 0.f) {
            y = (su[r] / se[r]) * inv_c2;     // su = c2 * sum(v*x)
        } else {           // all masked: uniform softmax -> mean(x) = sum(u)/(c2*N)
            float s = 0.f;
#pragma unroll
            for (int k = 0; k < 32; k++) s += xs[k * 32 + lane].x;
#pragma unroll
            for (int o = 16; o; o >>= 1) s += __shfl_xor_sync(0xFFFFFFFFu, s, o);
            y = s * inv_c2 * (1.0f / (float)N);
        }
        float4 ov;
        float v0 = y * wv.x; ov.x = v0 > 0.f ? v0 : expm1f(v0);
        float v1 = y * wv.y; ov.y = v1 > 0.f ? v1 : expm1f(v1);
        float v2 = y * wv.z; ov.z = v2 > 0.f ? v2 : expm1f(v2);
        float v3 = y * wv.w; ov.w = v3 > 0.f ? v3 : expm1f(v3);
        orow[r * (F / 4)] = ov;
    }
}

// ---------------------------------------------------------------------------
// Launch. Inputs (metadata order): input(32*1024), adj(1024*1024),
// ext_input(unused), side_input(unused), W(128), a(256). Output: (32,1024,128) f32.
// ---------------------------------------------------------------------------
extern "C" void kernel_launch(void* const* d_in, const int* in_sizes, int n_in,
                              void* d_out, int out_size) {
    const float* x   = (const float*)d_in[0];
    const int*   adj = (const int*)d_in[1];
    const float* W   = (const float*)d_in[4];
    const float* a   = (const float*)d_in[5];
    float* out = (float*)d_out;

    prep_kernel<<<N / 8 + BS, 256>>>(adj, x, W, a);
    dim3 grid(N / RPB, BS);
    gat_main_kernel<<<grid, THREADS>>>(W, out);
}